// round 10
// baseline (speedup 1.0000x reference)
#include <cuda_runtime.h>
#include <cuda_fp16.h>
#include <math.h>
#include <stdint.h>

#define T_TOK 2048
#define H_DIM 1024
#define E_NUM 8
#define I_DIM 2816
#define NSLOT (2*T_TOK)

// ---------------- device scratch ----------------
__device__ int   g_count[E_NUM];
__device__ int   g_base[E_NUM];
__device__ int   g_tok[E_NUM*T_TOK];
__device__ float g_wgt[NSLOT];
__device__ int   g_rowtok[NSLOT];
__device__ __half g_X[(size_t)NSLOT*H_DIM];
__device__ __half g_A[(size_t)NSLOT*I_DIM];

// ---------------- helpers ----------------
__device__ __forceinline__ uint32_t s2u(const void* p){
    uint32_t a;
    asm("{ .reg .u64 t; cvta.to.shared.u64 t, %1; cvt.u32.u64 %0, t; }" : "=r"(a) : "l"(p));
    return a;
}
__device__ __forceinline__ void cpa(uint32_t dst, const void* src){
    asm volatile("cp.async.cg.shared.global [%0], [%1], 16;" :: "r"(dst), "l"(src));
}
__device__ __forceinline__ void cpcommit(){ asm volatile("cp.async.commit_group;" ::: "memory"); }
template<int N> __device__ __forceinline__ void cpwait(){ asm volatile("cp.async.wait_group %0;" :: "n"(N) : "memory"); }

__device__ __forceinline__ void ldsm4(uint32_t* r, uint32_t a){
    asm volatile("ldmatrix.sync.aligned.m8n8.x4.shared.b16 {%0,%1,%2,%3}, [%4];"
        : "=r"(r[0]), "=r"(r[1]), "=r"(r[2]), "=r"(r[3]) : "r"(a));
}
__device__ __forceinline__ void ldsm4t(uint32_t* r, uint32_t a){
    asm volatile("ldmatrix.sync.aligned.m8n8.x4.trans.shared.b16 {%0,%1,%2,%3}, [%4];"
        : "=r"(r[0]), "=r"(r[1]), "=r"(r[2]), "=r"(r[3]) : "r"(a));
}
__device__ __forceinline__ void mma_f16(float* d, const uint32_t* a, const uint32_t* b){
    asm volatile(
        "mma.sync.aligned.m16n8k16.row.col.f32.f16.f16.f32 "
        "{%0,%1,%2,%3}, {%4,%5,%6,%7}, {%8,%9}, {%0,%1,%2,%3};"
        : "+f"(d[0]), "+f"(d[1]), "+f"(d[2]), "+f"(d[3])
        : "r"(a[0]), "r"(a[1]), "r"(a[2]), "r"(a[3]), "r"(b[0]), "r"(b[1]));
}
__device__ __forceinline__ uint32_t h2u(__half2 v){
    return *reinterpret_cast<uint32_t*>(&v);
}
__device__ __forceinline__ void roundf4h(float4 v, uint32_t& h0, uint32_t& h1){
    h0 = h2u(__floats2half2_rn(v.x, v.y));
    h1 = h2u(__floats2half2_rn(v.z, v.w));
}

// ---------------- small kernels ----------------
__global__ void k_zero(){ if (threadIdx.x < E_NUM) g_count[threadIdx.x] = 0; }

__global__ void k_router(const float* __restrict__ x, const float* __restrict__ wr){
    int t = blockIdx.x*8 + (threadIdx.x>>5);
    int lane = threadIdx.x & 31;
    if (t >= T_TOK) return;
    float acc[E_NUM];
#pragma unroll
    for (int e=0;e<E_NUM;e++) acc[e]=0.f;
    const float* xr = x + (size_t)t*H_DIM;
    for (int h=lane; h<H_DIM; h+=32){
        float xv = xr[h];
        const float* wrow = wr + (size_t)h*E_NUM;
#pragma unroll
        for (int e=0;e<E_NUM;e++) acc[e] += xv*wrow[e];
    }
#pragma unroll
    for (int off=16; off>0; off>>=1)
#pragma unroll
        for (int e=0;e<E_NUM;e++) acc[e] += __shfl_down_sync(0xFFFFFFFFu, acc[e], off);
    if (lane==0){
        int i0=0; float v0=acc[0];
#pragma unroll
        for (int e=1;e<E_NUM;e++) if (acc[e]>v0){ v0=acc[e]; i0=e; }
        int i1=-1; float v1=-INFINITY;
#pragma unroll
        for (int e=0;e<E_NUM;e++){ if (e==i0) continue; if (acc[e]>v1){ v1=acc[e]; i1=e; } }
        float w0 = 1.f/(1.f+expf(v1-v0));
        float w1 = 1.f - w0;
        int p0 = atomicAdd(&g_count[i0],1); g_tok[i0*T_TOK+p0] = 2*t;
        int p1 = atomicAdd(&g_count[i1],1); g_tok[i1*T_TOK+p1] = 2*t+1;
        g_wgt[2*t]=w0; g_wgt[2*t+1]=w1;
    }
}

__global__ void k_prefix(){
    if (threadIdx.x==0){
        int s=0;
#pragma unroll
        for (int e=0;e<E_NUM;e++){ g_base[e]=s; s+=g_count[e]; }
    }
}

__global__ void __launch_bounds__(256) k_prep(const float* __restrict__ x){
    int e = blockIdx.y, p = blockIdx.x;
    if (p >= g_count[e]) return;
    int r = g_base[e] + p;
    int slot = g_tok[e*T_TOK + p];
    if (threadIdx.x==0) g_rowtok[r] = slot;
    int t = slot >> 1;
    float4 v = ((const float4*)(x + (size_t)t*H_DIM))[threadIdx.x];
    uint32_t h0,h1;
    roundf4h(v, h0, h1);
    *(uint2*)(g_X + (size_t)r*H_DIM + threadIdx.x*4) = make_uint2(h0,h1);
}

// ======================== GEMM 1: gate+up (pure fp16, M=256 tile) ========================
// CTA 256(M) x 64(N), K chunks of 32, 16 warps (8M x 2N), warp tile 32x32, 512 threads.
// SMEM layout:
//   [0, 40960)        A stages: s*20480; 256 rows x 80B
//   [40960, 59392)    B fp16 stages: 40960 + s*9216; G+0, U+4608; [k=32][n=64], stride 144B
//   [59392, 94208)    B fp32 stages: 59392 + s*17408; gate+0, up+8704; stride 272B
#define GU_SMEM 94208
__global__ void __launch_bounds__(512,1) k_gemm_gateup(const float* __restrict__ wg,
                                                       const float* __restrict__ wu){
    const int e = blockIdx.z;
    const int cnt = g_count[e];
    const int m0 = blockIdx.x*256;
    if (m0 >= cnt) return;
    const int n0 = blockIdx.y*64;
    const int rowbase = g_base[e] + m0;
    const int vr = min(256, cnt - m0);

    extern __shared__ char sm[];
    uint32_t sb = s2u(sm);

    const int tid = threadIdx.x;
    const int lane = tid & 31, wid = tid >> 5;
    const int wm = wid & 7, wn = wid >> 3;
    const int r0 = lane >> 2;

    const uint32_t laneA  = (uint32_t)((wm*32 + ((lane>>3)&1)*8 + (lane&7))*80 + (lane>>4)*16);
    const uint32_t laneBT = (uint32_t)((lane&15)*144 + (lane>>4)*16);

    const char* xp = (const char*)g_X + (size_t)rowbase*H_DIM*2;
    const float* wg_p = wg + (size_t)e*H_DIM*I_DIM + n0;
    const float* wu_p = wu + (size_t)e*H_DIM*I_DIM + n0;

    const int brow = tid >> 4;         // 0..31
    const int bseg = tid & 15;         // 0..15

    float accG[2][4][4] = {};
    float accU[2][4][4] = {};

    auto issue_stage = [&](int kc){
        uint32_t astg = sb + (kc & 1)*20480;
        int kb = kc*64;
#pragma unroll
        for (int c=0;c<2;c++){   // A fp16: 1024 x 16B
            int idx = tid + 512*c;
            int row = idx >> 2, seg = idx & 3;
            int srow = min(rowbase + row, NSLOT-1) - rowbase;
            cpa(astg + row*80 + seg*16, xp + (size_t)srow*2048 + kb + seg*16);
        }
        int kr = kc*32;
        uint32_t fstg = sb + 59392 + (kc & 1)*17408;
#pragma unroll
        for (int m=0;m<2;m++){   // B fp32 (own-data mapping)
            const float* s = (m ? wu_p : wg_p) + (size_t)(kr + brow)*I_DIM + bseg*4;
            cpa(fstg + m*8704 + brow*272 + bseg*16, s);
        }
        cpcommit();
    };

    // each thread rounds exactly the fp32 bytes it cp.async'd (visible after cpwait)
    auto convert = [&](int kc){
        const char* fb = sm + 59392 + (kc & 1)*17408;
        char* bbn = sm + 40960 + (kc & 1)*9216;
#pragma unroll
        for (int m=0;m<2;m++){
            float4 v = *(const float4*)(fb + m*8704 + brow*272 + bseg*16);
            uint32_t h0,h1;
            roundf4h(v, h0, h1);
            *(uint2*)(bbn + m*4608 + brow*144 + bseg*8) = make_uint2(h0,h1);
        }
    };

    auto compute = [&](int kc){
        uint32_t aB = sb + (kc & 1)*20480 + laneA;
        uint32_t bBase = sb + 40960 + (kc & 1)*9216 + laneBT + (wn*64);
#pragma unroll
        for (int k16=0;k16<2;k16++){
            uint32_t ko = k16*32;
            uint32_t ah[2][4];
            ldsm4(ah[0], aB + ko);
            ldsm4(ah[1], aB + 1280 + ko);
#pragma unroll
            for (int np=0;np<2;np++){
                uint32_t bo = bBase + k16*2304 + np*32;
                uint32_t bg_[4], bu_[4];
                ldsm4t(bg_, bo);
                ldsm4t(bu_, bo + 4608);
#pragma unroll
                for (int s=0;s<2;s++){
                    int ni = np*2+s;
#pragma unroll
                    for (int mi=0;mi<2;mi++){
                        mma_f16(accG[mi][ni], ah[mi], bg_+2*s);
                        mma_f16(accU[mi][ni], ah[mi], bu_+2*s);
                    }
                }
            }
        }
    };

    issue_stage(0);
    cpwait<0>();
    convert(0);
    __syncthreads();

    const int NK = H_DIM/32;  // 32
    for (int kc=0; kc<NK; kc++){
        if (kc+1 < NK) issue_stage(kc+1);
        compute(kc);
        if (kc+1 < NK){
            cpwait<0>();
            convert(kc+1);
        }
        __syncthreads();
    }

    // epilogue: a = silu(g)*u -> g_A (fp16)
#pragma unroll
    for (int mi=0;mi<2;mi++)
#pragma unroll
        for (int hf=0;hf<2;hf++){
            int row = wm*32 + mi*16 + r0 + hf*8;
            if (row < vr){
                size_t rb = (size_t)(rowbase + row)*I_DIM;
#pragma unroll
                for (int ni=0;ni<4;ni++){
                    int n = n0 + wn*32 + ni*8 + (lane&3)*2;
                    float g0 = accG[mi][ni][hf*2+0], g1 = accG[mi][ni][hf*2+1];
                    float u0 = accU[mi][ni][hf*2+0], u1 = accU[mi][ni][hf*2+1];
                    float a0 = g0/(1.f+expf(-g0))*u0;
                    float a1 = g1/(1.f+expf(-g1))*u1;
                    *(uint32_t*)((char*)g_A + (rb+n)*2) = h2u(__floats2half2_rn(a0, a1));
                }
            }
        }
}

// ======================== GEMM 2: down (M=256 x N=128, single wave) ==============
// CTA 256(M) x 128(N), 16 warps (8M x 2N), warp tile 32x64, 512 threads.
// SMEM layout:
//   [0, 40960)        A stages: s*20480; 256 rows x 80B
//   [40960, 58368)    B fp16 stages: 40960 + s*8704; [k=32][n=128], stride 272B
//   [58368, 92160)    B fp32 stages: 58368 + s*16896; stride 528B
#define DN_SMEM 92160
__global__ void __launch_bounds__(512,1) k_gemm_down(const float* __restrict__ wd,
                                                     const float* __restrict__ bd,
                                                     float* __restrict__ out){
    const int e = blockIdx.z;
    const int cnt = g_count[e];
    const int m0 = blockIdx.x*256;
    if (m0 >= cnt) return;
    const int n0 = blockIdx.y*128;
    const int rowbase = g_base[e] + m0;
    const int vr = min(256, cnt - m0);

    extern __shared__ char sm[];
    uint32_t sb = s2u(sm);

    const int tid = threadIdx.x;
    const int lane = tid & 31, wid = tid >> 5;
    const int wm = wid & 7, wn = wid >> 3;
    const int r0 = lane >> 2;

    const uint32_t laneA  = (uint32_t)((wm*32 + ((lane>>3)&1)*8 + (lane&7))*80 + (lane>>4)*16);
    const uint32_t laneBT = (uint32_t)((lane&15)*272 + (lane>>4)*16);

    const char* ap = (const char*)g_A + (size_t)rowbase*I_DIM*2;
    const float* wd_p = wd + (size_t)e*I_DIM*H_DIM + n0;
    const size_t strA = (size_t)I_DIM*2;  // 5632

    const int brow = tid >> 4;   // 0..31
    const int bseg = tid & 15;   // 0..15

    float acc[2][8][4] = {};

    auto issue_stage = [&](int kc){
        uint32_t astg = sb + (kc & 1)*20480;
        int kb = kc*64;
#pragma unroll
        for (int c=0;c<2;c++){
            int idx = tid + 512*c;
            int row = idx >> 2, seg = idx & 3;
            int srow = min(rowbase + row, NSLOT-1) - rowbase;
            cpa(astg + row*80 + seg*16, ap + (size_t)srow*strA + kb + seg*16);
        }
        int kr = kc*32;
        uint32_t fstg = sb + 58368 + (kc & 1)*16896;
#pragma unroll
        for (int c=0;c<2;c++){   // B fp32: 32 rows x 32 segs (own-data)
            int seg = bseg + c*16;
            const float* s = wd_p + (size_t)(kr + brow)*H_DIM + seg*4;
            cpa(fstg + brow*528 + seg*16, s);
        }
        cpcommit();
    };

    auto convert = [&](int kc){
        const char* fb = sm + 58368 + (kc & 1)*16896;
        char* bbn = sm + 40960 + (kc & 1)*8704;
#pragma unroll
        for (int c=0;c<2;c++){
            int seg = bseg + c*16;
            float4 v = *(const float4*)(fb + brow*528 + seg*16);
            uint32_t h0,h1;
            roundf4h(v, h0, h1);
            *(uint2*)(bbn + brow*272 + seg*8) = make_uint2(h0,h1);
        }
    };

    auto compute = [&](int kc){
        uint32_t aB = sb + (kc & 1)*20480 + laneA;
        uint32_t bBase = sb + 40960 + (kc & 1)*8704 + laneBT + (wn*128);
#pragma unroll
        for (int k16=0;k16<2;k16++){
            uint32_t ah_[2][4];
            uint32_t ko = k16*32;
            ldsm4(ah_[0], aB + ko);
            ldsm4(ah_[1], aB + 1280 + ko);
#pragma unroll
            for (int np=0;np<4;np++){
                uint32_t bw_[4];
                ldsm4t(bw_, bBase + k16*4352 + np*32);
#pragma unroll
                for (int s=0;s<2;s++){
                    int ni = np*2+s;
#pragma unroll
                    for (int mi=0;mi<2;mi++){
                        mma_f16(acc[mi][ni], ah_[mi], bw_+2*s);
                    }
                }
            }
        }
    };

    issue_stage(0);
    cpwait<0>();
    convert(0);
    __syncthreads();

    const int NK = I_DIM/32;  // 88
    for (int kc=0; kc<NK; kc++){
        if (kc+1 < NK) issue_stage(kc+1);
        compute(kc);
        if (kc+1 < NK){
            cpwait<0>();
            convert(kc+1);
        }
        __syncthreads();
    }

    // epilogue: out[t] += w * (acc + b_down[e])   (2 commutative adds -> deterministic)
#pragma unroll
    for (int mi=0;mi<2;mi++)
#pragma unroll
        for (int hf=0;hf<2;hf++){
            int row = wm*32 + mi*16 + r0 + hf*8;
            if (row < vr){
                int slot = g_rowtok[rowbase + row];
                float w = g_wgt[slot];
                int t = slot >> 1;
                float* orow = out + (size_t)t*H_DIM;
                const float* brow_ = bd + (size_t)e*H_DIM;
#pragma unroll
                for (int ni=0;ni<8;ni++){
                    int n = n0 + wn*64 + ni*8 + (lane&3)*2;
                    float v0 = (acc[mi][ni][hf*2+0] + brow_[n])   * w;
                    float v1 = (acc[mi][ni][hf*2+1] + brow_[n+1]) * w;
                    atomicAdd(&orow[n],   v0);
                    atomicAdd(&orow[n+1], v1);
                }
            }
        }
}

// ---------------- launch ----------------
extern "C" void kernel_launch(void* const* d_in, const int* in_sizes, int n_in,
                              void* d_out, int out_size){
    const float* x  = (const float*)d_in[0];
    const float* wr = (const float*)d_in[1];
    const float* wg = (const float*)d_in[2];
    const float* wu = (const float*)d_in[3];
    const float* wd = (const float*)d_in[4];
    const float* bd = (const float*)d_in[5];
    float* out = (float*)d_out;

    cudaFuncSetAttribute(k_gemm_gateup, cudaFuncAttributeMaxDynamicSharedMemorySize, GU_SMEM);
    cudaFuncSetAttribute(k_gemm_down,   cudaFuncAttributeMaxDynamicSharedMemorySize, DN_SMEM);

    cudaMemsetAsync(out, 0, (size_t)out_size * sizeof(float));
    k_zero<<<1,32>>>();
    k_router<<<T_TOK/8, 256>>>(x, wr);
    k_prefix<<<1,32>>>();
    k_prep<<<dim3(T_TOK, E_NUM), 256>>>(x);

    // M=256 tiles: grid.x covers worst-case cnt=2048 -> 8 m-blocks
    k_gemm_gateup<<<dim3(8, I_DIM/64, E_NUM), 512, GU_SMEM>>>(wg, wu);
    k_gemm_down  <<<dim3(8, H_DIM/128, E_NUM), 512, DN_SMEM>>>(wd, bd, out);
}

// round 11
// speedup vs baseline: 1.3435x; 1.3435x over previous
#include <cuda_runtime.h>
#include <cuda_fp16.h>
#include <math.h>
#include <stdint.h>

#define T_TOK 2048
#define H_DIM 1024
#define E_NUM 8
#define I_DIM 2816
#define NSLOT (2*T_TOK)

// ---------------- device scratch ----------------
__device__ int   g_count[E_NUM];
__device__ int   g_base[E_NUM];
__device__ int   g_tok[E_NUM*T_TOK];
__device__ float g_wgt[NSLOT];
__device__ int   g_rowtok[NSLOT];
__device__ __half g_X[(size_t)NSLOT*H_DIM];
__device__ __half g_A[(size_t)NSLOT*I_DIM];

// ---------------- helpers ----------------
__device__ __forceinline__ uint32_t s2u(const void* p){
    uint32_t a;
    asm("{ .reg .u64 t; cvta.to.shared.u64 t, %1; cvt.u32.u64 %0, t; }" : "=r"(a) : "l"(p));
    return a;
}
__device__ __forceinline__ void cpa(uint32_t dst, const void* src){
    asm volatile("cp.async.cg.shared.global [%0], [%1], 16;" :: "r"(dst), "l"(src));
}
__device__ __forceinline__ void cpcommit(){ asm volatile("cp.async.commit_group;" ::: "memory"); }
template<int N> __device__ __forceinline__ void cpwait(){ asm volatile("cp.async.wait_group %0;" :: "n"(N) : "memory"); }

__device__ __forceinline__ void ldsm4(uint32_t* r, uint32_t a){
    asm volatile("ldmatrix.sync.aligned.m8n8.x4.shared.b16 {%0,%1,%2,%3}, [%4];"
        : "=r"(r[0]), "=r"(r[1]), "=r"(r[2]), "=r"(r[3]) : "r"(a));
}
__device__ __forceinline__ void ldsm4t(uint32_t* r, uint32_t a){
    asm volatile("ldmatrix.sync.aligned.m8n8.x4.trans.shared.b16 {%0,%1,%2,%3}, [%4];"
        : "=r"(r[0]), "=r"(r[1]), "=r"(r[2]), "=r"(r[3]) : "r"(a));
}
__device__ __forceinline__ void mma_f16(float* d, const uint32_t* a, const uint32_t* b){
    asm volatile(
        "mma.sync.aligned.m16n8k16.row.col.f32.f16.f16.f32 "
        "{%0,%1,%2,%3}, {%4,%5,%6,%7}, {%8,%9}, {%0,%1,%2,%3};"
        : "+f"(d[0]), "+f"(d[1]), "+f"(d[2]), "+f"(d[3])
        : "r"(a[0]), "r"(a[1]), "r"(a[2]), "r"(a[3]), "r"(b[0]), "r"(b[1]));
}
__device__ __forceinline__ uint32_t h2u(__half2 v){
    return *reinterpret_cast<uint32_t*>(&v);
}
__device__ __forceinline__ void roundf4h(float4 v, uint32_t& h0, uint32_t& h1){
    h0 = h2u(__floats2half2_rn(v.x, v.y));
    h1 = h2u(__floats2half2_rn(v.z, v.w));
}

// ---------------- small kernels ----------------
__global__ void k_zero(){ if (threadIdx.x < E_NUM) g_count[threadIdx.x] = 0; }

__global__ void k_router(const float* __restrict__ x, const float* __restrict__ wr){
    int t = blockIdx.x*8 + (threadIdx.x>>5);
    int lane = threadIdx.x & 31;
    if (t >= T_TOK) return;
    float acc[E_NUM];
#pragma unroll
    for (int e=0;e<E_NUM;e++) acc[e]=0.f;
    const float* xr = x + (size_t)t*H_DIM;
    for (int h=lane; h<H_DIM; h+=32){
        float xv = xr[h];
        const float* wrow = wr + (size_t)h*E_NUM;
#pragma unroll
        for (int e=0;e<E_NUM;e++) acc[e] += xv*wrow[e];
    }
#pragma unroll
    for (int off=16; off>0; off>>=1)
#pragma unroll
        for (int e=0;e<E_NUM;e++) acc[e] += __shfl_down_sync(0xFFFFFFFFu, acc[e], off);
    if (lane==0){
        int i0=0; float v0=acc[0];
#pragma unroll
        for (int e=1;e<E_NUM;e++) if (acc[e]>v0){ v0=acc[e]; i0=e; }
        int i1=-1; float v1=-INFINITY;
#pragma unroll
        for (int e=0;e<E_NUM;e++){ if (e==i0) continue; if (acc[e]>v1){ v1=acc[e]; i1=e; } }
        float w0 = 1.f/(1.f+expf(v1-v0));
        float w1 = 1.f - w0;
        int p0 = atomicAdd(&g_count[i0],1); g_tok[i0*T_TOK+p0] = 2*t;
        int p1 = atomicAdd(&g_count[i1],1); g_tok[i1*T_TOK+p1] = 2*t+1;
        g_wgt[2*t]=w0; g_wgt[2*t+1]=w1;
    }
}

__global__ void k_prefix(){
    if (threadIdx.x==0){
        int s=0;
#pragma unroll
        for (int e=0;e<E_NUM;e++){ g_base[e]=s; s+=g_count[e]; }
    }
}

__global__ void __launch_bounds__(256) k_prep(const float* __restrict__ x){
    int e = blockIdx.y, p = blockIdx.x;
    if (p >= g_count[e]) return;
    int r = g_base[e] + p;
    int slot = g_tok[e*T_TOK + p];
    if (threadIdx.x==0) g_rowtok[r] = slot;
    int t = slot >> 1;
    float4 v = ((const float4*)(x + (size_t)t*H_DIM))[threadIdx.x];
    uint32_t h0,h1;
    roundf4h(v, h0, h1);
    *(uint2*)(g_X + (size_t)r*H_DIM + threadIdx.x*4) = make_uint2(h0,h1);
}

// ======================== GEMM 1: gate+up (pure fp16, R9 config: M=128, 2 CTA/SM) ============
// CTA 128(M) x 64(N), K chunks of 32, 8 warps (4M x 2N), warp tile 32x32.
// SMEM layout:
//   [0, 20480)        A stages: s*10240; 128 rows x 80B
//   [20480, 38912)    B fp16 stages: 20480 + s*9216; G+0, U+4608; [k=32][n=64], stride 144B
//   [38912, 73728)    B fp32 stages: 38912 + s*17408; gate+0, up+8704; stride 272B
#define GU_SMEM 73728
__global__ void __launch_bounds__(256,2) k_gemm_gateup(const float* __restrict__ wg,
                                                       const float* __restrict__ wu){
    const int e = blockIdx.z;
    const int cnt = g_count[e];
    const int m0 = blockIdx.x*128;
    if (m0 >= cnt) return;
    const int n0 = blockIdx.y*64;
    const int rowbase = g_base[e] + m0;
    const int vr = min(128, cnt - m0);

    extern __shared__ char sm[];
    uint32_t sb = s2u(sm);

    const int tid = threadIdx.x;
    const int lane = tid & 31, wid = tid >> 5;
    const int wm = wid & 3, wn = wid >> 2;
    const int r0 = lane >> 2;

    const uint32_t laneA  = (uint32_t)((wm*32 + ((lane>>3)&1)*8 + (lane&7))*80 + (lane>>4)*16);
    const uint32_t laneBT = (uint32_t)((lane&15)*144 + (lane>>4)*16);

    const char* xp = (const char*)g_X + (size_t)rowbase*H_DIM*2;
    const float* wg_p = wg + (size_t)e*H_DIM*I_DIM + n0;
    const float* wu_p = wu + (size_t)e*H_DIM*I_DIM + n0;

    const int brow = tid >> 4;         // 0..15
    const int bseg = tid & 15;         // 0..15

    float accG[2][4][4] = {};
    float accU[2][4][4] = {};

    auto issue_stage = [&](int kc){
        uint32_t astg = sb + (kc & 1)*10240;
        int kb = kc*64;
#pragma unroll
        for (int c=0;c<2;c++){   // A fp16: 512 x 16B
            int idx = tid + 256*c;
            int row = idx >> 2, seg = idx & 3;
            int srow = min(rowbase + row, NSLOT-1) - rowbase;
            cpa(astg + row*80 + seg*16, xp + (size_t)srow*2048 + kb + seg*16);
        }
        int kr = kc*32;
        uint32_t fstg = sb + 38912 + (kc & 1)*17408;
#pragma unroll
        for (int c=0;c<4;c++){   // B fp32 (own-data mapping)
            int m = c >> 1, p = c & 1;
            int row = brow + p*16;
            const float* s = (m ? wu_p : wg_p) + (size_t)(kr + row)*I_DIM + bseg*4;
            cpa(fstg + m*8704 + row*272 + bseg*16, s);
        }
        cpcommit();
    };

    auto convert = [&](int kc){
        const char* fb = sm + 38912 + (kc & 1)*17408;
        char* bbn = sm + 20480 + (kc & 1)*9216;
#pragma unroll
        for (int m=0;m<2;m++){
#pragma unroll
            for (int p=0;p<2;p++){
                int row = brow + p*16;
                float4 v = *(const float4*)(fb + m*8704 + row*272 + bseg*16);
                uint32_t h0,h1;
                roundf4h(v, h0, h1);
                *(uint2*)(bbn + m*4608 + row*144 + bseg*8) = make_uint2(h0,h1);
            }
        }
    };

    auto compute = [&](int kc){
        uint32_t aB = sb + (kc & 1)*10240 + laneA;
        uint32_t bBase = sb + 20480 + (kc & 1)*9216 + laneBT + (wn*64);
#pragma unroll
        for (int k16=0;k16<2;k16++){
            uint32_t ko = k16*32;
            uint32_t ah[2][4];
            ldsm4(ah[0], aB + ko);
            ldsm4(ah[1], aB + 1280 + ko);
#pragma unroll
            for (int np=0;np<2;np++){
                uint32_t bo = bBase + k16*2304 + np*32;
                uint32_t bg_[4], bu_[4];
                ldsm4t(bg_, bo);
                ldsm4t(bu_, bo + 4608);
#pragma unroll
                for (int s=0;s<2;s++){
                    int ni = np*2+s;
#pragma unroll
                    for (int mi=0;mi<2;mi++){
                        mma_f16(accG[mi][ni], ah[mi], bg_+2*s);
                        mma_f16(accU[mi][ni], ah[mi], bu_+2*s);
                    }
                }
            }
        }
    };

    issue_stage(0);
    cpwait<0>();
    convert(0);
    __syncthreads();

    const int NK = H_DIM/32;  // 32
    for (int kc=0; kc<NK; kc++){
        if (kc+1 < NK) issue_stage(kc+1);
        compute(kc);
        if (kc+1 < NK){
            cpwait<0>();
            convert(kc+1);
        }
        __syncthreads();
    }

    // epilogue: a = silu(g)*u -> g_A (fp16)
#pragma unroll
    for (int mi=0;mi<2;mi++)
#pragma unroll
        for (int hf=0;hf<2;hf++){
            int row = wm*32 + mi*16 + r0 + hf*8;
            if (row < vr){
                size_t rb = (size_t)(rowbase + row)*I_DIM;
#pragma unroll
                for (int ni=0;ni<4;ni++){
                    int n = n0 + wn*32 + ni*8 + (lane&3)*2;
                    float g0 = accG[mi][ni][hf*2+0], g1 = accG[mi][ni][hf*2+1];
                    float u0 = accU[mi][ni][hf*2+0], u1 = accU[mi][ni][hf*2+1];
                    float a0 = g0/(1.f+expf(-g0))*u0;
                    float a1 = g1/(1.f+expf(-g1))*u1;
                    *(uint32_t*)((char*)g_A + (rb+n)*2) = h2u(__floats2half2_rn(a0, a1));
                }
            }
        }
}

// ======================== GEMM 2: down, M=128 x N=128, 256 thr, 2 CTA/SM ==============
// 8 warps (4M x 2N), warp tile 32x64 -> single wave (~256 CTAs vs 296 slots).
// SMEM layout:
//   [0, 20480)        A stages: s*10240; 128 rows x 80B
//   [20480, 37888)    B fp16 stages: 20480 + s*8704; [k=32][n=128], stride 272B
//   [37888, 71680)    B fp32 stages: 37888 + s*16896; stride 528B
#define DN_SMEM 71680
__global__ void __launch_bounds__(256,2) k_gemm_down(const float* __restrict__ wd,
                                                     const float* __restrict__ bd,
                                                     float* __restrict__ out){
    const int e = blockIdx.z;
    const int cnt = g_count[e];
    const int m0 = blockIdx.x*128;
    if (m0 >= cnt) return;
    const int n0 = blockIdx.y*128;
    const int rowbase = g_base[e] + m0;
    const int vr = min(128, cnt - m0);

    extern __shared__ char sm[];
    uint32_t sb = s2u(sm);

    const int tid = threadIdx.x;
    const int lane = tid & 31, wid = tid >> 5;
    const int wm = wid & 3, wn = wid >> 2;
    const int r0 = lane >> 2;

    const uint32_t laneA  = (uint32_t)((wm*32 + ((lane>>3)&1)*8 + (lane&7))*80 + (lane>>4)*16);
    const uint32_t laneBT = (uint32_t)((lane&15)*272 + (lane>>4)*16);

    const char* ap = (const char*)g_A + (size_t)rowbase*I_DIM*2;
    const float* wd_p = wd + (size_t)e*I_DIM*H_DIM + n0;
    const size_t strA = (size_t)I_DIM*2;  // 5632

    const int brow = tid >> 4;   // 0..15
    const int bseg = tid & 15;   // 0..15

    float acc[2][8][4] = {};

    auto issue_stage = [&](int kc){
        uint32_t astg = sb + (kc & 1)*10240;
        int kb = kc*64;
#pragma unroll
        for (int c=0;c<2;c++){   // A fp16: 512 x 16B
            int idx = tid + 256*c;
            int row = idx >> 2, seg = idx & 3;
            int srow = min(rowbase + row, NSLOT-1) - rowbase;
            cpa(astg + row*80 + seg*16, ap + (size_t)srow*strA + kb + seg*16);
        }
        int kr = kc*32;
        uint32_t fstg = sb + 37888 + (kc & 1)*16896;
#pragma unroll
        for (int c=0;c<4;c++){   // B fp32: rows {brow, brow+16} x segs {bseg, bseg+16}
            int row = brow + (c & 1)*16;
            int seg = bseg + (c >> 1)*16;
            const float* s = wd_p + (size_t)(kr + row)*H_DIM + seg*4;
            cpa(fstg + row*528 + seg*16, s);
        }
        cpcommit();
    };

    auto convert = [&](int kc){
        const char* fb = sm + 37888 + (kc & 1)*16896;
        char* bbn = sm + 20480 + (kc & 1)*8704;
#pragma unroll
        for (int c=0;c<4;c++){
            int row = brow + (c & 1)*16;
            int seg = bseg + (c >> 1)*16;
            float4 v = *(const float4*)(fb + row*528 + seg*16);
            uint32_t h0,h1;
            roundf4h(v, h0, h1);
            *(uint2*)(bbn + row*272 + seg*8) = make_uint2(h0,h1);
        }
    };

    auto compute = [&](int kc){
        uint32_t aB = sb + (kc & 1)*10240 + laneA;
        uint32_t bBase = sb + 20480 + (kc & 1)*8704 + laneBT + (wn*128);
#pragma unroll
        for (int k16=0;k16<2;k16++){
            uint32_t ah_[2][4];
            uint32_t ko = k16*32;
            ldsm4(ah_[0], aB + ko);
            ldsm4(ah_[1], aB + 1280 + ko);
#pragma unroll
            for (int np=0;np<4;np++){
                uint32_t bw_[4];
                ldsm4t(bw_, bBase + k16*4352 + np*32);
#pragma unroll
                for (int s=0;s<2;s++){
                    int ni = np*2+s;
#pragma unroll
                    for (int mi=0;mi<2;mi++){
                        mma_f16(acc[mi][ni], ah_[mi], bw_+2*s);
                    }
                }
            }
        }
    };

    issue_stage(0);
    cpwait<0>();
    convert(0);
    __syncthreads();

    const int NK = I_DIM/32;  // 88
    for (int kc=0; kc<NK; kc++){
        if (kc+1 < NK) issue_stage(kc+1);
        compute(kc);
        if (kc+1 < NK){
            cpwait<0>();
            convert(kc+1);
        }
        __syncthreads();
    }

    // epilogue: out[t] += w * (acc + b_down[e])   (2 commutative adds -> deterministic)
#pragma unroll
    for (int mi=0;mi<2;mi++)
#pragma unroll
        for (int hf=0;hf<2;hf++){
            int row = wm*32 + mi*16 + r0 + hf*8;
            if (row < vr){
                int slot = g_rowtok[rowbase + row];
                float w = g_wgt[slot];
                int t = slot >> 1;
                float* orow = out + (size_t)t*H_DIM;
                const float* brow_ = bd + (size_t)e*H_DIM;
#pragma unroll
                for (int ni=0;ni<8;ni++){
                    int n = n0 + wn*64 + ni*8 + (lane&3)*2;
                    float v0 = (acc[mi][ni][hf*2+0] + brow_[n])   * w;
                    float v1 = (acc[mi][ni][hf*2+1] + brow_[n+1]) * w;
                    atomicAdd(&orow[n],   v0);
                    atomicAdd(&orow[n+1], v1);
                }
            }
        }
}

// ---------------- launch ----------------
extern "C" void kernel_launch(void* const* d_in, const int* in_sizes, int n_in,
                              void* d_out, int out_size){
    const float* x  = (const float*)d_in[0];
    const float* wr = (const float*)d_in[1];
    const float* wg = (const float*)d_in[2];
    const float* wu = (const float*)d_in[3];
    const float* wd = (const float*)d_in[4];
    const float* bd = (const float*)d_in[5];
    float* out = (float*)d_out;

    cudaFuncSetAttribute(k_gemm_gateup, cudaFuncAttributeMaxDynamicSharedMemorySize, GU_SMEM);
    cudaFuncSetAttribute(k_gemm_down,   cudaFuncAttributeMaxDynamicSharedMemorySize, DN_SMEM);

    cudaMemsetAsync(out, 0, (size_t)out_size * sizeof(float));
    k_zero<<<1,32>>>();
    k_router<<<T_TOK/8, 256>>>(x, wr);
    k_prefix<<<1,32>>>();
    k_prep<<<dim3(T_TOK, E_NUM), 256>>>(x);

    k_gemm_gateup<<<dim3(T_TOK/128, I_DIM/64, E_NUM), 256, GU_SMEM>>>(wg, wu);
    k_gemm_down  <<<dim3(T_TOK/128, H_DIM/128, E_NUM), 256, DN_SMEM>>>(wd, bd, out);
}

// round 12
// speedup vs baseline: 1.5765x; 1.1734x over previous
#include <cuda_runtime.h>
#include <cuda_fp16.h>
#include <math.h>
#include <stdint.h>

#define T_TOK 2048
#define H_DIM 1024
#define E_NUM 8
#define I_DIM 2816
#define NSLOT (2*T_TOK)

// ---------------- device scratch ----------------
__device__ int   g_count[E_NUM];
__device__ int   g_base[E_NUM];
__device__ int   g_tok[E_NUM*T_TOK];
__device__ float g_wgt[NSLOT];
__device__ int   g_rowtok[NSLOT];
__device__ __half g_X[(size_t)NSLOT*H_DIM];
__device__ __half g_A[(size_t)NSLOT*I_DIM];

// ---------------- helpers ----------------
__device__ __forceinline__ uint32_t s2u(const void* p){
    uint32_t a;
    asm("{ .reg .u64 t; cvta.to.shared.u64 t, %1; cvt.u32.u64 %0, t; }" : "=r"(a) : "l"(p));
    return a;
}
__device__ __forceinline__ void cpa(uint32_t dst, const void* src){
    asm volatile("cp.async.cg.shared.global [%0], [%1], 16;" :: "r"(dst), "l"(src));
}
__device__ __forceinline__ void cpcommit(){ asm volatile("cp.async.commit_group;" ::: "memory"); }
template<int N> __device__ __forceinline__ void cpwait(){ asm volatile("cp.async.wait_group %0;" :: "n"(N) : "memory"); }

__device__ __forceinline__ void ldsm4(uint32_t* r, uint32_t a){
    asm volatile("ldmatrix.sync.aligned.m8n8.x4.shared.b16 {%0,%1,%2,%3}, [%4];"
        : "=r"(r[0]), "=r"(r[1]), "=r"(r[2]), "=r"(r[3]) : "r"(a));
}
__device__ __forceinline__ void ldsm4t(uint32_t* r, uint32_t a){
    asm volatile("ldmatrix.sync.aligned.m8n8.x4.trans.shared.b16 {%0,%1,%2,%3}, [%4];"
        : "=r"(r[0]), "=r"(r[1]), "=r"(r[2]), "=r"(r[3]) : "r"(a));
}
__device__ __forceinline__ void mma_f16(float* d, const uint32_t* a, const uint32_t* b){
    asm volatile(
        "mma.sync.aligned.m16n8k16.row.col.f32.f16.f16.f32 "
        "{%0,%1,%2,%3}, {%4,%5,%6,%7}, {%8,%9}, {%0,%1,%2,%3};"
        : "+f"(d[0]), "+f"(d[1]), "+f"(d[2]), "+f"(d[3])
        : "r"(a[0]), "r"(a[1]), "r"(a[2]), "r"(a[3]), "r"(b[0]), "r"(b[1]));
}
__device__ __forceinline__ uint32_t h2u(__half2 v){
    return *reinterpret_cast<uint32_t*>(&v);
}
__device__ __forceinline__ void roundf4h(float4 v, uint32_t& h0, uint32_t& h1){
    h0 = h2u(__floats2half2_rn(v.x, v.y));
    h1 = h2u(__floats2half2_rn(v.z, v.w));
}

// ---------------- small kernels ----------------
__global__ void k_zero(){ if (threadIdx.x < E_NUM) g_count[threadIdx.x] = 0; }

__global__ void k_router(const float* __restrict__ x, const float* __restrict__ wr){
    int t = blockIdx.x*8 + (threadIdx.x>>5);
    int lane = threadIdx.x & 31;
    if (t >= T_TOK) return;
    float acc[E_NUM];
#pragma unroll
    for (int e=0;e<E_NUM;e++) acc[e]=0.f;
    const float* xr = x + (size_t)t*H_DIM;
    for (int h=lane; h<H_DIM; h+=32){
        float xv = xr[h];
        const float* wrow = wr + (size_t)h*E_NUM;
#pragma unroll
        for (int e=0;e<E_NUM;e++) acc[e] += xv*wrow[e];
    }
#pragma unroll
    for (int off=16; off>0; off>>=1)
#pragma unroll
        for (int e=0;e<E_NUM;e++) acc[e] += __shfl_down_sync(0xFFFFFFFFu, acc[e], off);
    if (lane==0){
        int i0=0; float v0=acc[0];
#pragma unroll
        for (int e=1;e<E_NUM;e++) if (acc[e]>v0){ v0=acc[e]; i0=e; }
        int i1=-1; float v1=-INFINITY;
#pragma unroll
        for (int e=0;e<E_NUM;e++){ if (e==i0) continue; if (acc[e]>v1){ v1=acc[e]; i1=e; } }
        float w0 = 1.f/(1.f+expf(v1-v0));
        float w1 = 1.f - w0;
        int p0 = atomicAdd(&g_count[i0],1); g_tok[i0*T_TOK+p0] = 2*t;
        int p1 = atomicAdd(&g_count[i1],1); g_tok[i1*T_TOK+p1] = 2*t+1;
        g_wgt[2*t]=w0; g_wgt[2*t+1]=w1;
    }
}

__global__ void k_prefix(){
    if (threadIdx.x==0){
        int s=0;
#pragma unroll
        for (int e=0;e<E_NUM;e++){ g_base[e]=s; s+=g_count[e]; }
    }
}

// flat grid: one block per output row (all NSLOT rows are active)
__global__ void __launch_bounds__(256) k_prep(const float* __restrict__ x){
    int r = blockIdx.x;
    int e = 0;
#pragma unroll
    for (int i=1;i<E_NUM;i++) if (r >= g_base[i]) e = i;
    int p = r - g_base[e];
    int slot = g_tok[e*T_TOK + p];
    if (threadIdx.x==0) g_rowtok[r] = slot;
    int t = slot >> 1;
    float4 v = ((const float4*)(x + (size_t)t*H_DIM))[threadIdx.x];
    uint32_t h0,h1;
    roundf4h(v, h0, h1);
    *(uint2*)(g_X + (size_t)r*H_DIM + threadIdx.x*4) = make_uint2(h0,h1);
}

// ======================== GEMM 1: gate+up (pure fp16, K-chunk 64) ========================
// CTA 128(M) x 64(N), K chunks of 64, 8 warps (4M x 2N), warp tile 32x32.
// SMEM layout:
//   [0, 36864)        A stages: s*18432; 128 rows x 144B (128B data)
//   [36864, 73728)    B fp16 stages: 36864 + s*18432; G+0, U+9216; [k=64][n=64], stride 144B
//   [73728, 108544)   B fp32 SINGLE buffer: gate+0, up+17408; [k=64][n=64], stride 272B
#define GU_SMEM 108544
__global__ void __launch_bounds__(256,2) k_gemm_gateup(const float* __restrict__ wg,
                                                       const float* __restrict__ wu){
    const int e = blockIdx.z;
    const int cnt = g_count[e];
    const int m0 = blockIdx.x*128;
    if (m0 >= cnt) return;
    const int n0 = blockIdx.y*64;
    const int rowbase = g_base[e] + m0;
    const int vr = min(128, cnt - m0);

    extern __shared__ char sm[];
    uint32_t sb = s2u(sm);

    const int tid = threadIdx.x;
    const int lane = tid & 31, wid = tid >> 5;
    const int wm = wid & 3, wn = wid >> 2;
    const int r0 = lane >> 2;

    const uint32_t laneA  = (uint32_t)((wm*32 + ((lane>>3)&1)*8 + (lane&7))*144 + (lane>>4)*16);
    const uint32_t laneBT = (uint32_t)((lane&15)*144 + (lane>>4)*16);

    const char* xp = (const char*)g_X + (size_t)rowbase*H_DIM*2;
    const float* wg_p = wg + (size_t)e*H_DIM*I_DIM + n0;
    const float* wu_p = wu + (size_t)e*H_DIM*I_DIM + n0;

    const int brow = tid >> 4;         // 0..15
    const int bseg = tid & 15;         // 0..15

    float accG[2][4][4] = {};
    float accU[2][4][4] = {};

    auto issue_stage = [&](int kc){
        uint32_t astg = sb + (kc & 1)*18432;
        int kb = kc*128;   // 64 elems * 2B per chunk
#pragma unroll
        for (int c=0;c<4;c++){   // A fp16: 1024 x 16B
            int idx = tid + 256*c;
            int row = idx >> 3, seg = idx & 7;
            int srow = min(rowbase + row, NSLOT-1) - rowbase;
            cpa(astg + row*144 + seg*16, xp + (size_t)srow*2048 + kb + seg*16);
        }
        int kr = kc*64;
#pragma unroll
        for (int m=0;m<2;m++)    // B fp32 (own-data mapping): 8 cpa/thread
#pragma unroll
            for (int p=0;p<4;p++){
                int row = brow + p*16;
                const float* s = (m ? wu_p : wg_p) + (size_t)(kr + row)*I_DIM + bseg*4;
                cpa(sb + 73728 + m*17408 + row*272 + bseg*16, s);
            }
        cpcommit();
    };

    // each thread rounds exactly the fp32 bytes it cp.async'd (single fp32 buffer is safe)
    auto convert = [&](int kc){
        const char* fb = sm + 73728;
        char* bbn = sm + 36864 + (kc & 1)*18432;
#pragma unroll
        for (int m=0;m<2;m++)
#pragma unroll
            for (int p=0;p<4;p++){
                int row = brow + p*16;
                float4 v = *(const float4*)(fb + m*17408 + row*272 + bseg*16);
                uint32_t h0,h1;
                roundf4h(v, h0, h1);
                *(uint2*)(bbn + m*9216 + row*144 + bseg*8) = make_uint2(h0,h1);
            }
    };

    auto compute = [&](int kc){
        uint32_t aB = sb + (kc & 1)*18432 + laneA;
        uint32_t bBase = sb + 36864 + (kc & 1)*18432 + laneBT + (wn*64);
#pragma unroll
        for (int k16=0;k16<4;k16++){
            uint32_t ko = k16*32;     // A: 16 elems * 2B within row
            uint32_t ah[2][4];
            ldsm4(ah[0], aB + ko);
            ldsm4(ah[1], aB + 2304 + ko);       // +16 rows * 144B
#pragma unroll
            for (int np=0;np<2;np++){
                uint32_t bo = bBase + k16*2304 + np*32;   // B: +16 k-rows * 144B
                uint32_t bg_[4], bu_[4];
                ldsm4t(bg_, bo);
                ldsm4t(bu_, bo + 9216);
#pragma unroll
                for (int s=0;s<2;s++){
                    int ni = np*2+s;
#pragma unroll
                    for (int mi=0;mi<2;mi++){
                        mma_f16(accG[mi][ni], ah[mi], bg_+2*s);
                        mma_f16(accU[mi][ni], ah[mi], bu_+2*s);
                    }
                }
            }
        }
    };

    issue_stage(0);
    cpwait<0>();
    convert(0);
    __syncthreads();

    const int NK = H_DIM/64;  // 16
    for (int kc=0; kc<NK; kc++){
        if (kc+1 < NK) issue_stage(kc+1);
        compute(kc);
        if (kc+1 < NK){
            cpwait<0>();
            convert(kc+1);
        }
        __syncthreads();
    }

    // epilogue: a = silu(g)*u -> g_A (fp16)
#pragma unroll
    for (int mi=0;mi<2;mi++)
#pragma unroll
        for (int hf=0;hf<2;hf++){
            int row = wm*32 + mi*16 + r0 + hf*8;
            if (row < vr){
                size_t rb = (size_t)(rowbase + row)*I_DIM;
#pragma unroll
                for (int ni=0;ni<4;ni++){
                    int n = n0 + wn*32 + ni*8 + (lane&3)*2;
                    float g0 = accG[mi][ni][hf*2+0], g1 = accG[mi][ni][hf*2+1];
                    float u0 = accU[mi][ni][hf*2+0], u1 = accU[mi][ni][hf*2+1];
                    float a0 = g0/(1.f+expf(-g0))*u0;
                    float a1 = g1/(1.f+expf(-g1))*u1;
                    *(uint32_t*)((char*)g_A + (rb+n)*2) = h2u(__floats2half2_rn(a0, a1));
                }
            }
        }
}

// ======================== GEMM 2: down, M=128 x N=128, K-chunk 64 ==============
// 8 warps (4M x 2N), warp tile 32x64, single wave (~256 CTAs).
// SMEM layout:
//   [0, 36864)        A stages: s*18432; 128 rows x 144B
//   [36864, 71680)    B fp16 stages: 36864 + s*17408; [k=64][n=128], stride 272B
//   [71680, 105472)   B fp32 SINGLE buffer: [k=64][n=128], stride 528B
#define DN_SMEM 105472
__global__ void __launch_bounds__(256,2) k_gemm_down(const float* __restrict__ wd,
                                                     const float* __restrict__ bd,
                                                     float* __restrict__ out){
    const int e = blockIdx.z;
    const int cnt = g_count[e];
    const int m0 = blockIdx.x*128;
    if (m0 >= cnt) return;
    const int n0 = blockIdx.y*128;
    const int rowbase = g_base[e] + m0;
    const int vr = min(128, cnt - m0);

    extern __shared__ char sm[];
    uint32_t sb = s2u(sm);

    const int tid = threadIdx.x;
    const int lane = tid & 31, wid = tid >> 5;
    const int wm = wid & 3, wn = wid >> 2;
    const int r0 = lane >> 2;

    const uint32_t laneA  = (uint32_t)((wm*32 + ((lane>>3)&1)*8 + (lane&7))*144 + (lane>>4)*16);
    const uint32_t laneBT = (uint32_t)((lane&15)*272 + (lane>>4)*16);

    const char* ap = (const char*)g_A + (size_t)rowbase*I_DIM*2;
    const float* wd_p = wd + (size_t)e*I_DIM*H_DIM + n0;
    const size_t strA = (size_t)I_DIM*2;  // 5632

    const int brow = tid >> 4;   // 0..15
    const int bseg = tid & 15;   // 0..15

    float acc[2][8][4] = {};

    auto issue_stage = [&](int kc){
        uint32_t astg = sb + (kc & 1)*18432;
        int kb = kc*128;
#pragma unroll
        for (int c=0;c<4;c++){   // A fp16: 1024 x 16B
            int idx = tid + 256*c;
            int row = idx >> 3, seg = idx & 7;
            int srow = min(rowbase + row, NSLOT-1) - rowbase;
            cpa(astg + row*144 + seg*16, ap + (size_t)srow*strA + kb + seg*16);
        }
        int kr = kc*64;
#pragma unroll
        for (int p=0;p<4;p++)    // B fp32: rows {brow+16p} x segs {bseg, bseg+16}
#pragma unroll
            for (int q=0;q<2;q++){
                int row = brow + p*16;
                int seg = bseg + q*16;
                const float* s = wd_p + (size_t)(kr + row)*H_DIM + seg*4;
                cpa(sb + 71680 + row*528 + seg*16, s);
            }
        cpcommit();
    };

    auto convert = [&](int kc){
        const char* fb = sm + 71680;
        char* bbn = sm + 36864 + (kc & 1)*17408;
#pragma unroll
        for (int p=0;p<4;p++)
#pragma unroll
            for (int q=0;q<2;q++){
                int row = brow + p*16;
                int seg = bseg + q*16;
                float4 v = *(const float4*)(fb + row*528 + seg*16);
                uint32_t h0,h1;
                roundf4h(v, h0, h1);
                *(uint2*)(bbn + row*272 + seg*8) = make_uint2(h0,h1);
            }
    };

    auto compute = [&](int kc){
        uint32_t aB = sb + (kc & 1)*18432 + laneA;
        uint32_t bBase = sb + 36864 + (kc & 1)*17408 + laneBT + (wn*128);
#pragma unroll
        for (int k16=0;k16<4;k16++){
            uint32_t ah_[2][4];
            uint32_t ko = k16*32;
            ldsm4(ah_[0], aB + ko);
            ldsm4(ah_[1], aB + 2304 + ko);
#pragma unroll
            for (int np=0;np<4;np++){
                uint32_t bw_[4];
                ldsm4t(bw_, bBase + k16*4352 + np*32);   // +16 k-rows * 272B
#pragma unroll
                for (int s=0;s<2;s++){
                    int ni = np*2+s;
#pragma unroll
                    for (int mi=0;mi<2;mi++){
                        mma_f16(acc[mi][ni], ah_[mi], bw_+2*s);
                    }
                }
            }
        }
    };

    issue_stage(0);
    cpwait<0>();
    convert(0);
    __syncthreads();

    const int NK = I_DIM/64;  // 44
    for (int kc=0; kc<NK; kc++){
        if (kc+1 < NK) issue_stage(kc+1);
        compute(kc);
        if (kc+1 < NK){
            cpwait<0>();
            convert(kc+1);
        }
        __syncthreads();
    }

    // epilogue: out[t] += w * (acc + b_down[e])   (2 commutative adds -> deterministic)
#pragma unroll
    for (int mi=0;mi<2;mi++)
#pragma unroll
        for (int hf=0;hf<2;hf++){
            int row = wm*32 + mi*16 + r0 + hf*8;
            if (row < vr){
                int slot = g_rowtok[rowbase + row];
                float w = g_wgt[slot];
                int t = slot >> 1;
                float* orow = out + (size_t)t*H_DIM;
                const float* brow_ = bd + (size_t)e*H_DIM;
#pragma unroll
                for (int ni=0;ni<8;ni++){
                    int n = n0 + wn*64 + ni*8 + (lane&3)*2;
                    float v0 = (acc[mi][ni][hf*2+0] + brow_[n])   * w;
                    float v1 = (acc[mi][ni][hf*2+1] + brow_[n+1]) * w;
                    atomicAdd(&orow[n],   v0);
                    atomicAdd(&orow[n+1], v1);
                }
            }
        }
}

// ---------------- launch ----------------
extern "C" void kernel_launch(void* const* d_in, const int* in_sizes, int n_in,
                              void* d_out, int out_size){
    const float* x  = (const float*)d_in[0];
    const float* wr = (const float*)d_in[1];
    const float* wg = (const float*)d_in[2];
    const float* wu = (const float*)d_in[3];
    const float* wd = (const float*)d_in[4];
    const float* bd = (const float*)d_in[5];
    float* out = (float*)d_out;

    cudaFuncSetAttribute(k_gemm_gateup, cudaFuncAttributeMaxDynamicSharedMemorySize, GU_SMEM);
    cudaFuncSetAttribute(k_gemm_down,   cudaFuncAttributeMaxDynamicSharedMemorySize, DN_SMEM);

    cudaMemsetAsync(out, 0, (size_t)out_size * sizeof(float));
    k_zero<<<1,32>>>();
    k_router<<<T_TOK/8, 256>>>(x, wr);
    k_prefix<<<1,32>>>();
    k_prep<<<NSLOT, 256>>>(x);

    k_gemm_gateup<<<dim3(T_TOK/128, I_DIM/64, E_NUM), 256, GU_SMEM>>>(wg, wu);
    k_gemm_down  <<<dim3(T_TOK/128, H_DIM/128, E_NUM), 256, DN_SMEM>>>(wd, bd, out);
}

// round 13
// speedup vs baseline: 1.8328x; 1.1626x over previous
#include <cuda_runtime.h>
#include <cuda_fp16.h>
#include <math.h>
#include <stdint.h>

#define T_TOK 2048
#define H_DIM 1024
#define E_NUM 8
#define I_DIM 2816
#define NSLOT (2*T_TOK)

// ---------------- device scratch ----------------
__device__ int   g_count[E_NUM];
__device__ int   g_base[E_NUM];
__device__ int   g_tok[E_NUM*T_TOK];
__device__ float g_wgt[NSLOT];
__device__ int   g_rowtok[NSLOT];
__device__ __half g_X[(size_t)NSLOT*H_DIM];
__device__ __half g_A[(size_t)NSLOT*I_DIM];

// ---------------- helpers ----------------
__device__ __forceinline__ uint32_t s2u(const void* p){
    uint32_t a;
    asm("{ .reg .u64 t; cvta.to.shared.u64 t, %1; cvt.u32.u64 %0, t; }" : "=r"(a) : "l"(p));
    return a;
}
__device__ __forceinline__ void cpa(uint32_t dst, const void* src){
    asm volatile("cp.async.cg.shared.global [%0], [%1], 16;" :: "r"(dst), "l"(src));
}
__device__ __forceinline__ void cpcommit(){ asm volatile("cp.async.commit_group;" ::: "memory"); }
template<int N> __device__ __forceinline__ void cpwait(){ asm volatile("cp.async.wait_group %0;" :: "n"(N) : "memory"); }

__device__ __forceinline__ void ldsm4(uint32_t* r, uint32_t a){
    asm volatile("ldmatrix.sync.aligned.m8n8.x4.shared.b16 {%0,%1,%2,%3}, [%4];"
        : "=r"(r[0]), "=r"(r[1]), "=r"(r[2]), "=r"(r[3]) : "r"(a));
}
__device__ __forceinline__ void ldsm4t(uint32_t* r, uint32_t a){
    asm volatile("ldmatrix.sync.aligned.m8n8.x4.trans.shared.b16 {%0,%1,%2,%3}, [%4];"
        : "=r"(r[0]), "=r"(r[1]), "=r"(r[2]), "=r"(r[3]) : "r"(a));
}
__device__ __forceinline__ void mma_f16(float* d, const uint32_t* a, const uint32_t* b){
    asm volatile(
        "mma.sync.aligned.m16n8k16.row.col.f32.f16.f16.f32 "
        "{%0,%1,%2,%3}, {%4,%5,%6,%7}, {%8,%9}, {%0,%1,%2,%3};"
        : "+f"(d[0]), "+f"(d[1]), "+f"(d[2]), "+f"(d[3])
        : "r"(a[0]), "r"(a[1]), "r"(a[2]), "r"(a[3]), "r"(b[0]), "r"(b[1]));
}
__device__ __forceinline__ uint32_t h2u(__half2 v){
    return *reinterpret_cast<uint32_t*>(&v);
}
__device__ __forceinline__ void roundf4h(float4 v, uint32_t& h0, uint32_t& h1){
    h0 = h2u(__floats2half2_rn(v.x, v.y));
    h1 = h2u(__floats2half2_rn(v.z, v.w));
}

// ---------------- small kernels ----------------
__global__ void k_zero(){ if (threadIdx.x < E_NUM) g_count[threadIdx.x] = 0; }

__global__ void k_router(const float* __restrict__ x, const float* __restrict__ wr){
    int t = blockIdx.x*8 + (threadIdx.x>>5);
    int lane = threadIdx.x & 31;
    if (t >= T_TOK) return;
    float acc[E_NUM];
#pragma unroll
    for (int e=0;e<E_NUM;e++) acc[e]=0.f;
    const float* xr = x + (size_t)t*H_DIM;
    for (int h=lane; h<H_DIM; h+=32){
        float xv = xr[h];
        const float* wrow = wr + (size_t)h*E_NUM;
#pragma unroll
        for (int e=0;e<E_NUM;e++) acc[e] += xv*wrow[e];
    }
#pragma unroll
    for (int off=16; off>0; off>>=1)
#pragma unroll
        for (int e=0;e<E_NUM;e++) acc[e] += __shfl_down_sync(0xFFFFFFFFu, acc[e], off);
    if (lane==0){
        int i0=0; float v0=acc[0];
#pragma unroll
        for (int e=1;e<E_NUM;e++) if (acc[e]>v0){ v0=acc[e]; i0=e; }
        int i1=-1; float v1=-INFINITY;
#pragma unroll
        for (int e=0;e<E_NUM;e++){ if (e==i0) continue; if (acc[e]>v1){ v1=acc[e]; i1=e; } }
        float w0 = 1.f/(1.f+expf(v1-v0));
        float w1 = 1.f - w0;
        int p0 = atomicAdd(&g_count[i0],1); g_tok[i0*T_TOK+p0] = 2*t;
        int p1 = atomicAdd(&g_count[i1],1); g_tok[i1*T_TOK+p1] = 2*t+1;
        g_wgt[2*t]=w0; g_wgt[2*t+1]=w1;
    }
}

__global__ void k_prefix(){
    if (threadIdx.x==0){
        int s=0;
#pragma unroll
        for (int e=0;e<E_NUM;e++){ g_base[e]=s; s+=g_count[e]; }
    }
}

// flat grid: one block per output row
__global__ void __launch_bounds__(256) k_prep(const float* __restrict__ x){
    int r = blockIdx.x;
    int e = 0;
#pragma unroll
    for (int i=1;i<E_NUM;i++) if (r >= g_base[i]) e = i;
    int p = r - g_base[e];
    int slot = g_tok[e*T_TOK + p];
    if (threadIdx.x==0) g_rowtok[r] = slot;
    int t = slot >> 1;
    float4 v = ((const float4*)(x + (size_t)t*H_DIM))[threadIdx.x];
    uint32_t h0,h1;
    roundf4h(v, h0, h1);
    *(uint2*)(g_X + (size_t)r*H_DIM + threadIdx.x*4) = make_uint2(h0,h1);
}

// ======================== GEMM 1: gate+up (K-chunk 64, reg-convert B) ========================
// CTA 128(M) x 64(N), 8 warps (4M x 2N), warp tile 32x32.
// SMEM layout:
//   [0, 36864)        A stages: s*18432; 128 rows x 144B (128B data)
//   [36864, 73728)    B fp16 stages: 36864 + s*18432; G+0, U+9216; [k=64][n=64], stride 144B
#define GU_SMEM 73728
__global__ void __launch_bounds__(256,2) k_gemm_gateup(const float* __restrict__ wg,
                                                       const float* __restrict__ wu){
    const int e = blockIdx.z;
    const int cnt = g_count[e];
    const int m0 = blockIdx.x*128;
    if (m0 >= cnt) return;
    const int n0 = blockIdx.y*64;
    const int rowbase = g_base[e] + m0;
    const int vr = min(128, cnt - m0);

    extern __shared__ char sm[];
    uint32_t sb = s2u(sm);

    const int tid = threadIdx.x;
    const int lane = tid & 31, wid = tid >> 5;
    const int wm = wid & 3, wn = wid >> 2;
    const int r0 = lane >> 2;

    const uint32_t laneA  = (uint32_t)((wm*32 + ((lane>>3)&1)*8 + (lane&7))*144 + (lane>>4)*16);
    const uint32_t laneBT = (uint32_t)((lane&15)*144 + (lane>>4)*16);

    const char* xp = (const char*)g_X + (size_t)rowbase*H_DIM*2;
    const float* wg_p = wg + (size_t)e*H_DIM*I_DIM + n0;
    const float* wu_p = wu + (size_t)e*H_DIM*I_DIM + n0;

    const int brow = tid >> 4;         // 0..15
    const int bseg = tid & 15;         // 0..15

    float accG[2][4][4] = {};
    float accU[2][4][4] = {};

    auto issueA = [&](int kc){
        uint32_t astg = sb + (kc & 1)*18432;
        int kb = kc*128;
#pragma unroll
        for (int c=0;c<4;c++){
            int idx = tid + 256*c;
            int row = idx >> 3, seg = idx & 7;
            int srow = min(rowbase + row, NSLOT-1) - rowbase;
            cpa(astg + row*144 + seg*16, xp + (size_t)srow*2048 + kb + seg*16);
        }
        cpcommit();
    };

    // LDG one matrix batch (4 float4) of B fp32 for chunk kc
    auto ldgB = [&](int kc, int m, float4* v){
        int kr = kc*64;
        const float* base = m ? wu_p : wg_p;
#pragma unroll
        for (int p=0;p<4;p++)
            v[p] = *(const float4*)(base + (size_t)(kr + brow + p*16)*I_DIM + bseg*4);
    };
    // convert + store fp16 batch
    auto stsB = [&](int kc, int m, const float4* v){
        char* bbn = sm + 36864 + (kc & 1)*18432 + m*9216;
#pragma unroll
        for (int p=0;p<4;p++){
            uint32_t h0,h1;
            roundf4h(v[p], h0, h1);
            *(uint2*)(bbn + (brow + p*16)*144 + bseg*8) = make_uint2(h0,h1);
        }
    };

    // compute half h (k16 = 2h, 2h+1)
    auto compute_half = [&](int kc, int h){
        uint32_t aB = sb + (kc & 1)*18432 + laneA;
        uint32_t bBase = sb + 36864 + (kc & 1)*18432 + laneBT + (wn*64);
#pragma unroll
        for (int kk=0;kk<2;kk++){
            int k16 = 2*h + kk;
            uint32_t ko = k16*32;
            uint32_t ah[2][4];
            ldsm4(ah[0], aB + ko);
            ldsm4(ah[1], aB + 2304 + ko);
#pragma unroll
            for (int np=0;np<2;np++){
                uint32_t bo = bBase + k16*2304 + np*32;
                uint32_t bg_[4], bu_[4];
                ldsm4t(bg_, bo);
                ldsm4t(bu_, bo + 9216);
#pragma unroll
                for (int s=0;s<2;s++){
                    int ni = np*2+s;
#pragma unroll
                    for (int mi=0;mi<2;mi++){
                        mma_f16(accG[mi][ni], ah[mi], bg_+2*s);
                        mma_f16(accU[mi][ni], ah[mi], bu_+2*s);
                    }
                }
            }
        }
    };

    // prologue: stage 0
    {
        issueA(0);
        float4 vb[4];
        ldgB(0, 0, vb); stsB(0, 0, vb);
        ldgB(0, 1, vb); stsB(0, 1, vb);
        cpwait<0>();
        __syncthreads();
    }

    const int NK = H_DIM/64;  // 16
    for (int kc=0; kc<NK; kc++){
        bool more = (kc+1 < NK);
        if (more) issueA(kc+1);
        float4 vb[4];
        if (more) ldgB(kc+1, 0, vb);     // LDGs fly during compute
        compute_half(kc, 0);
        if (more){ stsB(kc+1, 0, vb); ldgB(kc+1, 1, vb); }
        compute_half(kc, 1);
        if (more){ stsB(kc+1, 1, vb); cpwait<0>(); }
        __syncthreads();
    }

    // epilogue: a = silu(g)*u -> g_A (fp16)
#pragma unroll
    for (int mi=0;mi<2;mi++)
#pragma unroll
        for (int hf=0;hf<2;hf++){
            int row = wm*32 + mi*16 + r0 + hf*8;
            if (row < vr){
                size_t rb = (size_t)(rowbase + row)*I_DIM;
#pragma unroll
                for (int ni=0;ni<4;ni++){
                    int n = n0 + wn*32 + ni*8 + (lane&3)*2;
                    float g0 = accG[mi][ni][hf*2+0], g1 = accG[mi][ni][hf*2+1];
                    float u0 = accU[mi][ni][hf*2+0], u1 = accU[mi][ni][hf*2+1];
                    float a0 = g0/(1.f+expf(-g0))*u0;
                    float a1 = g1/(1.f+expf(-g1))*u1;
                    *(uint32_t*)((char*)g_A + (rb+n)*2) = h2u(__floats2half2_rn(a0, a1));
                }
            }
        }
}

// ======================== GEMM 2: down (K-chunk 64, N=128, reg-convert B) ==============
// 8 warps (4M x 2N), warp tile 32x64, single wave.
// SMEM layout:
//   [0, 36864)        A stages: s*18432; 128 rows x 144B
//   [36864, 71680)    B fp16 stages: 36864 + s*17408; [k=64][n=128], stride 272B
#define DN_SMEM 71680
__global__ void __launch_bounds__(256,2) k_gemm_down(const float* __restrict__ wd,
                                                     const float* __restrict__ bd,
                                                     float* __restrict__ out){
    const int e = blockIdx.z;
    const int cnt = g_count[e];
    const int m0 = blockIdx.x*128;
    if (m0 >= cnt) return;
    const int n0 = blockIdx.y*128;
    const int rowbase = g_base[e] + m0;
    const int vr = min(128, cnt - m0);

    extern __shared__ char sm[];
    uint32_t sb = s2u(sm);

    const int tid = threadIdx.x;
    const int lane = tid & 31, wid = tid >> 5;
    const int wm = wid & 3, wn = wid >> 2;
    const int r0 = lane >> 2;

    const uint32_t laneA  = (uint32_t)((wm*32 + ((lane>>3)&1)*8 + (lane&7))*144 + (lane>>4)*16);
    const uint32_t laneBT = (uint32_t)((lane&15)*272 + (lane>>4)*16);

    const char* ap = (const char*)g_A + (size_t)rowbase*I_DIM*2;
    const float* wd_p = wd + (size_t)e*I_DIM*H_DIM + n0;
    const size_t strA = (size_t)I_DIM*2;  // 5632

    const int brow = tid >> 4;   // 0..15
    const int bseg = tid & 15;   // 0..15

    float acc[2][8][4] = {};

    auto issueA = [&](int kc){
        uint32_t astg = sb + (kc & 1)*18432;
        int kb = kc*128;
#pragma unroll
        for (int c=0;c<4;c++){
            int idx = tid + 256*c;
            int row = idx >> 3, seg = idx & 7;
            int srow = min(rowbase + row, NSLOT-1) - rowbase;
            cpa(astg + row*144 + seg*16, ap + (size_t)srow*strA + kb + seg*16);
        }
        cpcommit();
    };

    // B fp32 batch b (2 k-rows x 2 segs = 4 float4) for chunk kc
    auto ldgB = [&](int kc, int b, float4* v){
        int kr = kc*64;
#pragma unroll
        for (int i=0;i<2;i++)
#pragma unroll
            for (int q=0;q<2;q++){
                int row = brow + (b*2 + i)*16;
                int seg = bseg + q*16;
                v[i*2+q] = *(const float4*)(wd_p + (size_t)(kr + row)*H_DIM + seg*4);
            }
    };
    auto stsB = [&](int kc, int b, const float4* v){
        char* bbn = sm + 36864 + (kc & 1)*17408;
#pragma unroll
        for (int i=0;i<2;i++)
#pragma unroll
            for (int q=0;q<2;q++){
                int row = brow + (b*2 + i)*16;
                int seg = bseg + q*16;
                uint32_t h0,h1;
                roundf4h(v[i*2+q], h0, h1);
                *(uint2*)(bbn + row*272 + seg*8) = make_uint2(h0,h1);
            }
    };

    auto compute_half = [&](int kc, int h){
        uint32_t aB = sb + (kc & 1)*18432 + laneA;
        uint32_t bBase = sb + 36864 + (kc & 1)*17408 + laneBT + (wn*128);
#pragma unroll
        for (int kk=0;kk<2;kk++){
            int k16 = 2*h + kk;
            uint32_t ah_[2][4];
            uint32_t ko = k16*32;
            ldsm4(ah_[0], aB + ko);
            ldsm4(ah_[1], aB + 2304 + ko);
#pragma unroll
            for (int np=0;np<4;np++){
                uint32_t bw_[4];
                ldsm4t(bw_, bBase + k16*4352 + np*32);
#pragma unroll
                for (int s=0;s<2;s++){
                    int ni = np*2+s;
#pragma unroll
                    for (int mi=0;mi<2;mi++){
                        mma_f16(acc[mi][ni], ah_[mi], bw_+2*s);
                    }
                }
            }
        }
    };

    {
        issueA(0);
        float4 vb[4];
        ldgB(0, 0, vb); stsB(0, 0, vb);
        ldgB(0, 1, vb); stsB(0, 1, vb);
        cpwait<0>();
        __syncthreads();
    }

    const int NK = I_DIM/64;  // 44
    for (int kc=0; kc<NK; kc++){
        bool more = (kc+1 < NK);
        if (more) issueA(kc+1);
        float4 vb[4];
        if (more) ldgB(kc+1, 0, vb);
        compute_half(kc, 0);
        if (more){ stsB(kc+1, 0, vb); ldgB(kc+1, 1, vb); }
        compute_half(kc, 1);
        if (more){ stsB(kc+1, 1, vb); cpwait<0>(); }
        __syncthreads();
    }

    // epilogue: out[t] += w * (acc + b_down[e])   (2 commutative adds -> deterministic)
#pragma unroll
    for (int mi=0;mi<2;mi++)
#pragma unroll
        for (int hf=0;hf<2;hf++){
            int row = wm*32 + mi*16 + r0 + hf*8;
            if (row < vr){
                int slot = g_rowtok[rowbase + row];
                float w = g_wgt[slot];
                int t = slot >> 1;
                float* orow = out + (size_t)t*H_DIM;
                const float* brow_ = bd + (size_t)e*H_DIM;
#pragma unroll
                for (int ni=0;ni<8;ni++){
                    int n = n0 + wn*64 + ni*8 + (lane&3)*2;
                    float v0 = (acc[mi][ni][hf*2+0] + brow_[n])   * w;
                    float v1 = (acc[mi][ni][hf*2+1] + brow_[n+1]) * w;
                    atomicAdd(&orow[n],   v0);
                    atomicAdd(&orow[n+1], v1);
                }
            }
        }
}

// ---------------- launch ----------------
extern "C" void kernel_launch(void* const* d_in, const int* in_sizes, int n_in,
                              void* d_out, int out_size){
    const float* x  = (const float*)d_in[0];
    const float* wr = (const float*)d_in[1];
    const float* wg = (const float*)d_in[2];
    const float* wu = (const float*)d_in[3];
    const float* wd = (const float*)d_in[4];
    const float* bd = (const float*)d_in[5];
    float* out = (float*)d_out;

    cudaFuncSetAttribute(k_gemm_gateup, cudaFuncAttributeMaxDynamicSharedMemorySize, GU_SMEM);
    cudaFuncSetAttribute(k_gemm_down,   cudaFuncAttributeMaxDynamicSharedMemorySize, DN_SMEM);

    cudaMemsetAsync(out, 0, (size_t)out_size * sizeof(float));
    k_zero<<<1,32>>>();
    k_router<<<T_TOK/8, 256>>>(x, wr);
    k_prefix<<<1,32>>>();
    k_prep<<<NSLOT, 256>>>(x);

    k_gemm_gateup<<<dim3(T_TOK/128, I_DIM/64, E_NUM), 256, GU_SMEM>>>(wg, wu);
    k_gemm_down  <<<dim3(T_TOK/128, H_DIM/128, E_NUM), 256, DN_SMEM>>>(wd, bd, out);
}